// round 1
// baseline (speedup 1.0000x reference)
#include <cuda_runtime.h>
#include <math.h>

#define BATCH 32768
#define STEPS 1000
#define HID   512
#define NT    64          // coarse t-grid points over [0,1]
#define GY    512         // y-grid points
#define DT_F  0.001f
#define SIGMA_C 0.5f
#define MU_C    1.0f
#define YLO  (-11.3f)
#define YHI  (14.3f)
#define CHUNK 40          // 1000 = 25 * 40, 40*4B = 160B (16B aligned)
#define SIM_BLOCKS 128

// scratch (static device arrays are allowed; no runtime allocation)
__device__ float g_Fc[NT * GY];        // coarse table f(t_i, y_g)
__device__ float g_F[STEPS * GY];      // per-step table f(t_s, y_g)
__device__ float g_part[SIM_BLOCKS];   // logqp block partials

// ---------------------------------------------------------------------------
// Kernel 1: build coarse table.  Each warp computes 4 rows (4 (t,y) points):
// full fp32 MLP eval: h1 = tanh([t,y]@W1+b1) -> z2 = h1@W2+b2 -> f = tanh(z2)@W3+b3
// h1 staged in smem (broadcast LDS.128), W2 streamed coalesced from L2.
// ---------------------------------------------------------------------------
__global__ void build_table(const float* __restrict__ W1, const float* __restrict__ b1,
                            const float* __restrict__ W2, const float* __restrict__ b2,
                            const float* __restrict__ W3, const float* __restrict__ b3)
{
    __shared__ float h1s[4][4][HID];   // [warp][row][j]  = 32 KB
    const int warp = threadIdx.x >> 5;
    const int lane = threadIdx.x & 31;
    const int task = blockIdx.x * 4 + warp;     // 0 .. 8191
    const int m0 = task * 4;                    // 4 rows per warp
    const float HY = (YHI - YLO) / (float)(GY - 1);
    const float HT = 1.0f / (float)(NT - 1);

    // stage h1 for the 4 rows
    #pragma unroll
    for (int r = 0; r < 4; ++r) {
        int m = m0 + r;
        int ti = m / GY;
        int gi = m - ti * GY;
        float t  = (float)ti * HT;
        float yv = YLO + (float)gi * HY;
        for (int j = lane; j < HID; j += 32) {
            h1s[warp][r][j] = tanhf(t * W1[j] + yv * W1[HID + j] + b1[j]);
        }
    }
    __syncwarp();

    const float4* h0 = (const float4*)h1s[warp][0];
    const float4* h1p = (const float4*)h1s[warp][1];
    const float4* h2p = (const float4*)h1s[warp][2];
    const float4* h3p = (const float4*)h1s[warp][3];

    float fs0 = 0.f, fs1 = 0.f, fs2 = 0.f, fs3 = 0.f;

    for (int kc = 0; kc < HID / 32; ++kc) {
        const int k = kc * 32 + lane;
        float a0 = b2[k], a1 = a0, a2 = a0, a3 = a0;
        const float* __restrict__ wcol = W2 + k;
        #pragma unroll 4
        for (int j4 = 0; j4 < HID / 4; ++j4) {
            float4 v0 = h0[j4], v1 = h1p[j4], v2 = h2p[j4], v3 = h3p[j4];
            const float* wr = wcol + (j4 * 4) * HID;
            float w;
            w = wr[0];
            a0 += v0.x * w; a1 += v1.x * w; a2 += v2.x * w; a3 += v3.x * w;
            w = wr[HID];
            a0 += v0.y * w; a1 += v1.y * w; a2 += v2.y * w; a3 += v3.y * w;
            w = wr[2 * HID];
            a0 += v0.z * w; a1 += v1.z * w; a2 += v2.z * w; a3 += v3.z * w;
            w = wr[3 * HID];
            a0 += v0.w * w; a1 += v1.w * w; a2 += v2.w * w; a3 += v3.w * w;
        }
        float wk = W3[k];
        fs0 += tanhf(a0) * wk;
        fs1 += tanhf(a1) * wk;
        fs2 += tanhf(a2) * wk;
        fs3 += tanhf(a3) * wk;
    }

    // warp reductions (deterministic)
    #pragma unroll
    for (int off = 16; off > 0; off >>= 1) {
        fs0 += __shfl_xor_sync(0xFFFFFFFFu, fs0, off);
        fs1 += __shfl_xor_sync(0xFFFFFFFFu, fs1, off);
        fs2 += __shfl_xor_sync(0xFFFFFFFFu, fs2, off);
        fs3 += __shfl_xor_sync(0xFFFFFFFFu, fs3, off);
    }
    if (lane == 0) {
        float bb = b3[0];
        g_Fc[m0 + 0] = fs0 + bb;
        g_Fc[m0 + 1] = fs1 + bb;
        g_Fc[m0 + 2] = fs2 + bb;
        g_Fc[m0 + 3] = fs3 + bb;
    }
}

// ---------------------------------------------------------------------------
// Kernel 2: expand coarse (t) grid to per-step table via 4-pt Lagrange in t.
// ---------------------------------------------------------------------------
__global__ void expand_table()
{
    int idx = blockIdx.x * blockDim.x + threadIdx.x;
    if (idx >= STEPS * GY) return;
    int s = idx / GY;
    int g = idx - s * GY;
    float t = (float)s * DT_F;
    float xf = t * (float)(NT - 1);
    int i = (int)floorf(xf);
    i = min(max(i, 1), NT - 3);
    float a = xf - (float)i;
    float wm1 = -a * (a - 1.f) * (a - 2.f) * (1.f / 6.f);
    float w0  = (a + 1.f) * (a - 1.f) * (a - 2.f) * 0.5f;
    float w1  = -(a + 1.f) * a * (a - 2.f) * 0.5f;
    float w2  = (a + 1.f) * a * (a - 1.f) * (1.f / 6.f);
    g_F[idx] = wm1 * g_Fc[(i - 1) * GY + g] + w0 * g_Fc[i * GY + g]
             + w1  * g_Fc[(i + 1) * GY + g] + w2 * g_Fc[(i + 2) * GY + g];
}

// ---------------------------------------------------------------------------
// Kernel 3: simulation. One thread per batch sample, all 1000 steps.
// Register-buffered output (40 steps) -> contiguous float4 stores.
// ---------------------------------------------------------------------------
__global__ void __launch_bounds__(256) sim_kernel(
    const float* __restrict__ eps, const float* __restrict__ dW,
    const float* __restrict__ qm, const float* __restrict__ qlv,
    float* __restrict__ out)
{
    const int b = blockIdx.x * 256 + threadIdx.x;
    float y = qm[0] + eps[b] * expf(0.5f * qlv[0]);
    float lq = 0.f;
    const float invH = (float)(GY - 1) / (YHI - YLO);
    float buf[CHUNK];

    for (int s0 = 0; s0 < STEPS; s0 += CHUNK) {
        #pragma unroll
        for (int ii = 0; ii < CHUNK; ++ii) {
            const int s = s0 + ii;
            float yc = fminf(fmaxf(y, YLO), YHI);
            float xf = (yc - YLO) * invH;
            int i = (int)xf;
            i = min(max(i, 1), GY - 3);
            float a = xf - (float)i;
            const float* __restrict__ row = g_F + s * GY;
            float f0 = row[i - 1], f1 = row[i], f2 = row[i + 1], f3 = row[i + 2];
            float wm1 = -a * (a - 1.f) * (a - 2.f) * (1.f / 6.f);
            float w0  = (a + 1.f) * (a - 1.f) * (a - 2.f) * 0.5f;
            float w1  = -(a + 1.f) * a * (a - 2.f) * 0.5f;
            float w2  = (a + 1.f) * a * (a - 1.f) * (1.f / 6.f);
            float f = wm1 * f0 + w0 * f1 + w1 * f2 + w2 * f3;
            // u = (f_post - theta*(mu - y)) / sigma ; theta=1, sigma=0.5
            float u = (f - (MU_C - y)) * 2.0f;
            lq += u * u * (0.5f * DT_F);
            y = y + f * DT_F + SIGMA_C * dW[s * BATCH + b];
            buf[ii] = y;
        }
        float4* dst = (float4*)(out + (size_t)b * STEPS + s0);
        #pragma unroll
        for (int q = 0; q < CHUNK / 4; ++q)
            dst[q] = make_float4(buf[4 * q], buf[4 * q + 1], buf[4 * q + 2], buf[4 * q + 3]);
    }

    // deterministic block reduction of logqp
    __shared__ float red[256];
    red[threadIdx.x] = lq;
    __syncthreads();
    #pragma unroll
    for (int off = 128; off > 0; off >>= 1) {
        if (threadIdx.x < off) red[threadIdx.x] += red[threadIdx.x + off];
        __syncthreads();
    }
    if (threadIdx.x == 0) g_part[blockIdx.x] = red[0];
}

// ---------------------------------------------------------------------------
// Kernel 4: finalize -> logpq scalar at out[BATCH*STEPS]
// ---------------------------------------------------------------------------
__global__ void finalize_kernel(const float* __restrict__ qm,
                                const float* __restrict__ qlv,
                                float* __restrict__ out)
{
    __shared__ float red[SIM_BLOCKS];
    int t = threadIdx.x;
    red[t] = g_part[t];
    __syncthreads();
    #pragma unroll
    for (int off = SIM_BLOCKS / 2; off > 0; off >>= 1) {
        if (t < off) red[t] += red[t + off];
        __syncthreads();
    }
    if (t == 0) {
        float qstd  = expf(0.5f * qlv[0]);
        float pystd = SIGMA_C / sqrtf(2.0f);   // sigma / sqrt(2*theta)
        float r = qstd / pystd;
        float dm = MU_C - qm[0];
        float kl0 = 0.5f * (r * r + dm * dm / (pystd * pystd) - 1.0f + logf(pystd / qstd));
        out[(size_t)BATCH * STEPS] = kl0 + red[0] / (float)BATCH;
    }
}

// ---------------------------------------------------------------------------
extern "C" void kernel_launch(void* const* d_in, const int* in_sizes, int n_in,
                              void* d_out, int out_size)
{
    const float* W1  = (const float*)d_in[0];
    const float* b1  = (const float*)d_in[1];
    const float* W2  = (const float*)d_in[2];
    const float* b2  = (const float*)d_in[3];
    const float* W3  = (const float*)d_in[4];
    const float* b3  = (const float*)d_in[5];
    const float* qm  = (const float*)d_in[6];
    const float* qlv = (const float*)d_in[7];
    const float* eps = (const float*)d_in[8];
    const float* dW  = (const float*)d_in[9];
    float* out = (float*)d_out;

    // 8192 warp-tasks of 4 rows each -> 2048 blocks x 4 warps
    build_table<<<2048, 128>>>(W1, b1, W2, b2, W3, b3);
    expand_table<<<(STEPS * GY + 255) / 256, 256>>>();
    sim_kernel<<<SIM_BLOCKS, 256>>>(eps, dW, qm, qlv, out);
    finalize_kernel<<<1, SIM_BLOCKS>>>(qm, qlv, out);
}

// round 2
// speedup vs baseline: 2.1305x; 2.1305x over previous
#include <cuda_runtime.h>
#include <math.h>

#define BATCH 32768
#define STEPS 1000
#define HID   512
#define NT    32          // coarse t-grid points over [0,1]
#define GY    256         // y-grid points
#define DT_F  0.001f
#define SIGMA_C 0.5f
#define MU_C    1.0f
#define YLO  (-11.3f)
#define YHI  (14.3f)
#define CHUNK 40          // 1000 = 25 * 40, 40*4B = 160B (16B aligned)
#define SIM_BLOCKS 128
#define ROWS_PER_WARP 8
#define WARPS_PER_BLOCK 2

// scratch (static device arrays are allowed; no runtime allocation)
__device__ float g_Fc[NT * GY];        // coarse table f(t_i, y_g)
__device__ float g_F[STEPS * GY];      // per-step table f(t_s, y_g)
__device__ float g_part[SIM_BLOCKS];   // logqp block partials

// ---------------------------------------------------------------------------
// Kernel 1: build coarse table. Each warp computes 8 rows (8 (t,y) points):
// full fp32 MLP eval: h1 = tanh([t,y]@W1+b1) -> z2 = h1@W2+b2 -> f = tanh(z2)@W3+b3
// h1 staged in smem (lane-uniform broadcast LDS.128), W2 streamed once per warp.
// ---------------------------------------------------------------------------
__global__ void __launch_bounds__(32 * WARPS_PER_BLOCK)
build_table(const float* __restrict__ W1, const float* __restrict__ b1,
            const float* __restrict__ W2, const float* __restrict__ b2,
            const float* __restrict__ W3, const float* __restrict__ b3)
{
    __shared__ float h1s[WARPS_PER_BLOCK][ROWS_PER_WARP][HID];   // 32 KB
    const int warp = threadIdx.x >> 5;
    const int lane = threadIdx.x & 31;
    const int task = blockIdx.x * WARPS_PER_BLOCK + warp;  // 0 .. 1023
    const int m0 = task * ROWS_PER_WARP;                   // 8 rows per warp
    const float HY = (YHI - YLO) / (float)(GY - 1);
    const float HT = 1.0f / (float)(NT - 1);

    // stage h1 for the 8 rows
    #pragma unroll
    for (int r = 0; r < ROWS_PER_WARP; ++r) {
        int m = m0 + r;
        int ti = m / GY;
        int gi = m - ti * GY;
        float t  = (float)ti * HT;
        float yv = YLO + (float)gi * HY;
        for (int j = lane; j < HID; j += 32) {
            h1s[warp][r][j] = tanhf(t * W1[j] + yv * W1[HID + j] + b1[j]);
        }
    }
    __syncwarp();

    const float4* hp[ROWS_PER_WARP];
    #pragma unroll
    for (int r = 0; r < ROWS_PER_WARP; ++r)
        hp[r] = (const float4*)h1s[warp][r];

    float fs[ROWS_PER_WARP];
    #pragma unroll
    for (int r = 0; r < ROWS_PER_WARP; ++r) fs[r] = 0.f;

    for (int kc = 0; kc < HID / 32; ++kc) {
        const int k = kc * 32 + lane;
        float a[ROWS_PER_WARP];
        float bk = b2[k];
        #pragma unroll
        for (int r = 0; r < ROWS_PER_WARP; ++r) a[r] = bk;

        const float* __restrict__ wcol = W2 + k;
        #pragma unroll 2
        for (int j4 = 0; j4 < HID / 4; ++j4) {
            float4 v[ROWS_PER_WARP];
            #pragma unroll
            for (int r = 0; r < ROWS_PER_WARP; ++r) v[r] = hp[r][j4];
            const float* wr = wcol + (j4 * 4) * HID;
            float w;
            w = wr[0];
            #pragma unroll
            for (int r = 0; r < ROWS_PER_WARP; ++r) a[r] += v[r].x * w;
            w = wr[HID];
            #pragma unroll
            for (int r = 0; r < ROWS_PER_WARP; ++r) a[r] += v[r].y * w;
            w = wr[2 * HID];
            #pragma unroll
            for (int r = 0; r < ROWS_PER_WARP; ++r) a[r] += v[r].z * w;
            w = wr[3 * HID];
            #pragma unroll
            for (int r = 0; r < ROWS_PER_WARP; ++r) a[r] += v[r].w * w;
        }
        float wk = W3[k];
        #pragma unroll
        for (int r = 0; r < ROWS_PER_WARP; ++r)
            fs[r] += tanhf(a[r]) * wk;
    }

    // deterministic warp reductions
    #pragma unroll
    for (int off = 16; off > 0; off >>= 1) {
        #pragma unroll
        for (int r = 0; r < ROWS_PER_WARP; ++r)
            fs[r] += __shfl_xor_sync(0xFFFFFFFFu, fs[r], off);
    }
    if (lane == 0) {
        float bb = b3[0];
        #pragma unroll
        for (int r = 0; r < ROWS_PER_WARP; ++r)
            g_Fc[m0 + r] = fs[r] + bb;
    }
}

// ---------------------------------------------------------------------------
// Kernel 2: expand coarse (t) grid to per-step table via 4-pt Lagrange in t.
// ---------------------------------------------------------------------------
__global__ void expand_table()
{
    int idx = blockIdx.x * blockDim.x + threadIdx.x;
    if (idx >= STEPS * GY) return;
    int s = idx / GY;
    int g = idx - s * GY;
    float t = (float)s * DT_F;
    float xf = t * (float)(NT - 1);
    int i = (int)floorf(xf);
    i = min(max(i, 1), NT - 3);
    float a = xf - (float)i;
    float wm1 = -a * (a - 1.f) * (a - 2.f) * (1.f / 6.f);
    float w0  = (a + 1.f) * (a - 1.f) * (a - 2.f) * 0.5f;
    float w1  = -(a + 1.f) * a * (a - 2.f) * 0.5f;
    float w2  = (a + 1.f) * a * (a - 1.f) * (1.f / 6.f);
    g_F[idx] = wm1 * g_Fc[(i - 1) * GY + g] + w0 * g_Fc[i * GY + g]
             + w1  * g_Fc[(i + 1) * GY + g] + w2 * g_Fc[(i + 2) * GY + g];
}

// ---------------------------------------------------------------------------
// Kernel 3: simulation. One thread per batch sample, all 1000 steps.
// dW front-batched per 40-step chunk (MLP for DRAM stream); table taps hit L1
// (1 KB row/step, all warps on an SM walk the same rows). Register-buffered
// output -> contiguous float4 stores.
// ---------------------------------------------------------------------------
__global__ void __launch_bounds__(256) sim_kernel(
    const float* __restrict__ eps, const float* __restrict__ dW,
    const float* __restrict__ qm, const float* __restrict__ qlv,
    float* __restrict__ out)
{
    const int b = blockIdx.x * 256 + threadIdx.x;
    float y = qm[0] + eps[b] * expf(0.5f * qlv[0]);
    float lq = 0.f;
    const float invH = (float)(GY - 1) / (YHI - YLO);
    float buf[CHUNK];
    float dwbuf[CHUNK];

    for (int s0 = 0; s0 < STEPS; s0 += CHUNK) {
        // front-batched DRAM loads (independent, high MLP)
        #pragma unroll
        for (int ii = 0; ii < CHUNK; ++ii)
            dwbuf[ii] = dW[(size_t)(s0 + ii) * BATCH + b];

        #pragma unroll
        for (int ii = 0; ii < CHUNK; ++ii) {
            const int s = s0 + ii;
            float yc = fminf(fmaxf(y, YLO), YHI);
            float xf = (yc - YLO) * invH;
            int i = (int)xf;
            i = min(max(i, 1), GY - 3);
            float a = xf - (float)i;
            const float* __restrict__ row = g_F + s * GY;
            float f0 = row[i - 1], f1 = row[i], f2 = row[i + 1], f3 = row[i + 2];
            float wm1 = -a * (a - 1.f) * (a - 2.f) * (1.f / 6.f);
            float w0  = (a + 1.f) * (a - 1.f) * (a - 2.f) * 0.5f;
            float w1  = -(a + 1.f) * a * (a - 2.f) * 0.5f;
            float w2  = (a + 1.f) * a * (a - 1.f) * (1.f / 6.f);
            float f = wm1 * f0 + w0 * f1 + w1 * f2 + w2 * f3;
            // u = (f_post - theta*(mu - y)) / sigma ; theta=1, sigma=0.5
            float u = (f - (MU_C - y)) * 2.0f;
            lq += u * u * (0.5f * DT_F);
            y = y + f * DT_F + SIGMA_C * dwbuf[ii];
            buf[ii] = y;
        }
        float4* dst = (float4*)(out + (size_t)b * STEPS + s0);
        #pragma unroll
        for (int q = 0; q < CHUNK / 4; ++q)
            dst[q] = make_float4(buf[4 * q], buf[4 * q + 1], buf[4 * q + 2], buf[4 * q + 3]);
    }

    // deterministic block reduction of logqp
    __shared__ float red[256];
    red[threadIdx.x] = lq;
    __syncthreads();
    #pragma unroll
    for (int off = 128; off > 0; off >>= 1) {
        if (threadIdx.x < off) red[threadIdx.x] += red[threadIdx.x + off];
        __syncthreads();
    }
    if (threadIdx.x == 0) g_part[blockIdx.x] = red[0];
}

// ---------------------------------------------------------------------------
// Kernel 4: finalize -> logpq scalar at out[BATCH*STEPS]
// ---------------------------------------------------------------------------
__global__ void finalize_kernel(const float* __restrict__ qm,
                                const float* __restrict__ qlv,
                                float* __restrict__ out)
{
    __shared__ float red[SIM_BLOCKS];
    int t = threadIdx.x;
    red[t] = g_part[t];
    __syncthreads();
    #pragma unroll
    for (int off = SIM_BLOCKS / 2; off > 0; off >>= 1) {
        if (t < off) red[t] += red[t + off];
        __syncthreads();
    }
    if (t == 0) {
        float qstd  = expf(0.5f * qlv[0]);
        float pystd = SIGMA_C / sqrtf(2.0f);   // sigma / sqrt(2*theta)
        float r = qstd / pystd;
        float dm = MU_C - qm[0];
        float kl0 = 0.5f * (r * r + dm * dm / (pystd * pystd) - 1.0f + logf(pystd / qstd));
        out[(size_t)BATCH * STEPS] = kl0 + red[0] / (float)BATCH;
    }
}

// ---------------------------------------------------------------------------
extern "C" void kernel_launch(void* const* d_in, const int* in_sizes, int n_in,
                              void* d_out, int out_size)
{
    const float* W1  = (const float*)d_in[0];
    const float* b1  = (const float*)d_in[1];
    const float* W2  = (const float*)d_in[2];
    const float* b2  = (const float*)d_in[3];
    const float* W3  = (const float*)d_in[4];
    const float* b3  = (const float*)d_in[5];
    const float* qm  = (const float*)d_in[6];
    const float* qlv = (const float*)d_in[7];
    const float* eps = (const float*)d_in[8];
    const float* dW  = (const float*)d_in[9];
    float* out = (float*)d_out;

    // 1024 warp-tasks of 8 rows each -> 512 blocks x 2 warps
    build_table<<<NT * GY / (ROWS_PER_WARP * WARPS_PER_BLOCK), 32 * WARPS_PER_BLOCK>>>(
        W1, b1, W2, b2, W3, b3);
    expand_table<<<(STEPS * GY + 255) / 256, 256>>>();
    sim_kernel<<<SIM_BLOCKS, 256>>>(eps, dW, qm, qlv, out);
    finalize_kernel<<<1, SIM_BLOCKS>>>(qm, qlv, out);
}

// round 3
// speedup vs baseline: 4.6689x; 2.1915x over previous
#include <cuda_runtime.h>
#include <math.h>

#define BATCH 32768
#define STEPS 1000
#define HID   512
#define NT    16          // coarse t-grid points over [0,1]
#define GY    256         // y-grid points
#define DT_F  0.001f
#define YLO  (-9.5f)
#define YHI  (11.5f)
#define CHUNK 8           // steps per smem-staged chunk (1000 = 125*8)
#define NCHUNK (STEPS / CHUNK)
#define SIM_BLOCKS 256
#define SIM_THREADS 128
#define MAGIC 12582912.0f   // 1.5 * 2^23

// scratch (static device arrays; no runtime allocation)
__device__ float g_Fc[NT * GY];        // coarse table f(t_i, y_g)
__device__ float g_F[STEPS * GY];      // per-step table f(t_s, y_g)
__device__ float g_part[SIM_BLOCKS];   // logqp block partials

// ---------------------------------------------------------------------------
// Kernel 1: build coarse table. One block = 8 grid points; h1 staged once in
// smem; 4 warps split the k (output-neuron) dimension 128-wide each, so W2 is
// streamed once per BLOCK. Warp partials combined via smem (deterministic).
// ---------------------------------------------------------------------------
__global__ void __launch_bounds__(128)
build_table(const float* __restrict__ W1, const float* __restrict__ b1,
            const float* __restrict__ W2, const float* __restrict__ b2,
            const float* __restrict__ W3, const float* __restrict__ b3)
{
    __shared__ __align__(16) float h1s[8][HID];   // 16 KB
    __shared__ float part[4][8];
    const int tid  = threadIdx.x;
    const int warp = tid >> 5;
    const int lane = tid & 31;
    const int m0   = blockIdx.x * 8;

    // stage h1 = tanh([t,y] @ W1 + b1) for the 8 rows, cooperatively
    for (int idx = tid; idx < 8 * HID; idx += 128) {
        int r = idx >> 9;               // HID = 512
        int j = idx & (HID - 1);
        int m = m0 + r;
        float t  = (float)(m >> 8) * (1.0f / (float)(NT - 1));   // GY = 256
        float yv = YLO + (float)(m & (GY - 1)) * ((YHI - YLO) / (float)(GY - 1));
        h1s[r][j] = tanhf(t * W1[j] + yv * W1[HID + j] + b1[j]);
    }
    __syncthreads();

    const int kbase = warp * 128;
    float fs[8];
    #pragma unroll
    for (int r = 0; r < 8; ++r) fs[r] = 0.f;

    #pragma unroll
    for (int kc = 0; kc < 4; ++kc) {
        const int k = kbase + kc * 32 + lane;
        float a[8];
        float bk = b2[k];
        #pragma unroll
        for (int r = 0; r < 8; ++r) a[r] = bk;

        const float* __restrict__ wcol = W2 + k;
        #pragma unroll 2
        for (int j4 = 0; j4 < HID / 4; ++j4) {
            float4 v[8];
            #pragma unroll
            for (int r = 0; r < 8; ++r)
                v[r] = ((const float4*)h1s[r])[j4];   // lane-uniform broadcast
            const float* wr = wcol + (j4 * 4) * HID;
            float w;
            w = wr[0];
            #pragma unroll
            for (int r = 0; r < 8; ++r) a[r] += v[r].x * w;
            w = wr[HID];
            #pragma unroll
            for (int r = 0; r < 8; ++r) a[r] += v[r].y * w;
            w = wr[2 * HID];
            #pragma unroll
            for (int r = 0; r < 8; ++r) a[r] += v[r].z * w;
            w = wr[3 * HID];
            #pragma unroll
            for (int r = 0; r < 8; ++r) a[r] += v[r].w * w;
        }
        float wk = W3[k];
        #pragma unroll
        for (int r = 0; r < 8; ++r)
            fs[r] += tanhf(a[r]) * wk;
    }

    // deterministic lane reduction, then cross-warp combine via smem
    #pragma unroll
    for (int off = 16; off > 0; off >>= 1) {
        #pragma unroll
        for (int r = 0; r < 8; ++r)
            fs[r] += __shfl_xor_sync(0xFFFFFFFFu, fs[r], off);
    }
    if (lane == 0) {
        #pragma unroll
        for (int r = 0; r < 8; ++r) part[warp][r] = fs[r];
    }
    __syncthreads();
    if (tid < 8) {
        g_Fc[m0 + tid] = part[0][tid] + part[1][tid] + part[2][tid]
                       + part[3][tid] + b3[0];
    }
}

// ---------------------------------------------------------------------------
// Kernel 2: expand coarse (t) grid to per-step table via 4-pt Lagrange in t.
// ---------------------------------------------------------------------------
__global__ void expand_table()
{
    int idx = blockIdx.x * blockDim.x + threadIdx.x;
    if (idx >= STEPS * GY) return;
    int s = idx / GY;
    int g = idx - s * GY;
    float t = (float)s * DT_F;
    float xf = t * (float)(NT - 1);
    int i = (int)floorf(xf);
    i = min(max(i, 1), NT - 3);
    float a = xf - (float)i;
    float wm1 = -a * (a - 1.f) * (a - 2.f) * (1.f / 6.f);
    float w0  = (a + 1.f) * (a - 1.f) * (a - 2.f) * 0.5f;
    float w1  = -(a + 1.f) * a * (a - 2.f) * 0.5f;
    float w2  = (a + 1.f) * a * (a - 1.f) * (1.f / 6.f);
    g_F[idx] = wm1 * g_Fc[(i - 1) * GY + g] + w0 * g_Fc[i * GY + g]
             + w1  * g_Fc[(i + 1) * GY + g] + w2 * g_Fc[(i + 2) * GY + g];
}

// ---------------------------------------------------------------------------
// Kernel 3: simulation. One thread per sample, all 1000 steps.
// Step-rows staged in smem with double-buffered register prefetch (L2 latency
// hidden); magic-number floor (no F2I/I2F on the critical chain); dW
// front-batched; register-buffered output -> contiguous float4 stores.
// ---------------------------------------------------------------------------
__global__ void __launch_bounds__(SIM_THREADS)
sim_kernel(const float* __restrict__ eps, const float* __restrict__ dW,
           const float* __restrict__ qm, const float* __restrict__ qlv,
           float* __restrict__ out)
{
    __shared__ __align__(16) float rows[2][CHUNK][GY];  // 16 KB
    __shared__ float red[SIM_THREADS];
    const int tid = threadIdx.x;
    const int b = blockIdx.x * SIM_THREADS + tid;

    float y = qm[0] + eps[b] * expf(0.5f * qlv[0]);
    float lq = 0.f;
    const float invH = (float)(GY - 1) / (YHI - YLO);

    const float4* gF4 = (const float4*)g_F;
    const int F4C = CHUNK * GY / 4;           // float4 per chunk = 512
    const int QN  = F4C / SIM_THREADS;        // 4 per thread

    // load chunk 0
    #pragma unroll
    for (int q = 0; q < QN; ++q)
        ((float4*)rows[0])[tid + SIM_THREADS * q] = gF4[tid + SIM_THREADS * q];
    __syncthreads();

    for (int c = 0; c < NCHUNK; ++c) {
        const int cur = c & 1;
        const int s0 = c * CHUNK;

        // prefetch next chunk into registers (latency hidden by the 8 steps)
        float4 pf[QN];
        if (c + 1 < NCHUNK) {
            #pragma unroll
            for (int q = 0; q < QN; ++q)
                pf[q] = gF4[(c + 1) * F4C + tid + SIM_THREADS * q];
        }

        // front-batched dW loads (DRAM stream, high MLP)
        float dwbuf[CHUNK];
        #pragma unroll
        for (int ii = 0; ii < CHUNK; ++ii)
            dwbuf[ii] = dW[(size_t)(s0 + ii) * BATCH + b];

        float buf[CHUNK];
        #pragma unroll
        for (int ii = 0; ii < CHUNK; ++ii) {
            float xf = (y - YLO) * invH;
            xf = fminf(fmaxf(xf, 0.501f), (float)(GY - 3) + 0.499f);
            float mg = xf + MAGIC;                    // round-to-nearest i
            int i = __float_as_int(mg) & 0xFFFF;      // mantissa low bits = i
            float fi = mg - MAGIC;
            float a = xf - fi;                        // a in [-0.5, 0.5]
            const float* __restrict__ r_ = rows[cur][ii];
            float f0 = r_[i - 1], f1 = r_[i], f2 = r_[i + 1], f3 = r_[i + 2];
            float wm1 = -a * (a - 1.f) * (a - 2.f) * (1.f / 6.f);
            float w0  = (a + 1.f) * (a - 1.f) * (a - 2.f) * 0.5f;
            float w1  = -(a + 1.f) * a * (a - 2.f) * 0.5f;
            float w2  = (a + 1.f) * a * (a - 1.f) * (1.f / 6.f);
            float f = (wm1 * f0 + w0 * f1) + (w1 * f2 + w2 * f3);
            // u = (f_post - theta*(mu - y)) / sigma ; theta=1, mu=1, sigma=0.5
            float u = (f - 1.0f + y) * 2.0f;
            lq += u * u * (0.5f * DT_F);
            y = fmaf(f, DT_F, y) + 0.5f * dwbuf[ii];
            buf[ii] = y;
        }

        float4* dst = (float4*)(out + (size_t)b * STEPS + s0);
        dst[0] = make_float4(buf[0], buf[1], buf[2], buf[3]);
        dst[1] = make_float4(buf[4], buf[5], buf[6], buf[7]);

        // commit prefetched chunk into the other smem buffer
        if (c + 1 < NCHUNK) {
            #pragma unroll
            for (int q = 0; q < QN; ++q)
                ((float4*)rows[cur ^ 1])[tid + SIM_THREADS * q] = pf[q];
        }
        __syncthreads();
    }

    // deterministic block reduction of logqp
    red[tid] = lq;
    __syncthreads();
    #pragma unroll
    for (int off = SIM_THREADS / 2; off > 0; off >>= 1) {
        if (tid < off) red[tid] += red[tid + off];
        __syncthreads();
    }
    if (tid == 0) g_part[blockIdx.x] = red[0];
}

// ---------------------------------------------------------------------------
// Kernel 4: finalize -> logpq scalar at out[BATCH*STEPS]
// ---------------------------------------------------------------------------
__global__ void finalize_kernel(const float* __restrict__ qm,
                                const float* __restrict__ qlv,
                                float* __restrict__ out)
{
    __shared__ float red[SIM_BLOCKS];
    int t = threadIdx.x;
    red[t] = g_part[t];
    __syncthreads();
    #pragma unroll
    for (int off = SIM_BLOCKS / 2; off > 0; off >>= 1) {
        if (t < off) red[t] += red[t + off];
        __syncthreads();
    }
    if (t == 0) {
        float qstd  = expf(0.5f * qlv[0]);
        float pystd = 0.5f / sqrtf(2.0f);   // sigma / sqrt(2*theta)
        float r = qstd / pystd;
        float dm = 1.0f - qm[0];            // mu - qy0_mean
        float kl0 = 0.5f * (r * r + dm * dm / (pystd * pystd) - 1.0f + logf(pystd / qstd));
        out[(size_t)BATCH * STEPS] = kl0 + red[0] / (float)BATCH;
    }
}

// ---------------------------------------------------------------------------
extern "C" void kernel_launch(void* const* d_in, const int* in_sizes, int n_in,
                              void* d_out, int out_size)
{
    const float* W1  = (const float*)d_in[0];
    const float* b1  = (const float*)d_in[1];
    const float* W2  = (const float*)d_in[2];
    const float* b2  = (const float*)d_in[3];
    const float* W3  = (const float*)d_in[4];
    const float* b3  = (const float*)d_in[5];
    const float* qm  = (const float*)d_in[6];
    const float* qlv = (const float*)d_in[7];
    const float* eps = (const float*)d_in[8];
    const float* dW  = (const float*)d_in[9];
    float* out = (float*)d_out;

    build_table<<<NT * GY / 8, 128>>>(W1, b1, W2, b2, W3, b3);
    expand_table<<<(STEPS * GY + 255) / 256, 256>>>();
    sim_kernel<<<SIM_BLOCKS, SIM_THREADS>>>(eps, dW, qm, qlv, out);
    finalize_kernel<<<1, SIM_BLOCKS>>>(qm, qlv, out);
}

// round 4
// speedup vs baseline: 5.1000x; 1.0923x over previous
#include <cuda_runtime.h>
#include <math.h>
#include <stdint.h>

#define BATCH 32768
#define STEPS 1000
#define HID   512
#define NT    16           // coarse t-grid points over [0,1]
#define GY    128          // y-grid points
#define DT_F  0.001f
#define YLO  (-9.5f)
#define YHI  (11.5f)
#define CHUNK 8            // steps per smem-staged chunk (1000 = 125*8)
#define NCHUNK (STEPS / CHUNK)
#define SIM_BLOCKS 256
#define SIM_THREADS 128
#define MAGIC 12582912.0f  // 1.5 * 2^23

// scratch (static device arrays; no runtime allocation)
__device__ float g_Fc[NT * GY];            // coarse table f(t_i, y_g)
__device__ float g_Fv[STEPS * GY];         // per-step node values
__device__ float4 g_C[STEPS * GY];         // per-step per-cell cubic coeffs
__device__ float g_part[SIM_BLOCKS];       // logqp block partials

__device__ __forceinline__ void cp_async16(uint32_t saddr, const void* gaddr) {
    asm volatile("cp.async.cg.shared.global [%0], [%1], 16;\n" :: "r"(saddr), "l"(gaddr));
}
__device__ __forceinline__ void cp_commit() {
    asm volatile("cp.async.commit_group;\n");
}
template <int N>
__device__ __forceinline__ void cp_wait() {
    asm volatile("cp.async.wait_group %0;\n" :: "n"(N));
}

// ---------------------------------------------------------------------------
// Kernel 1: build coarse table. One block = 8 grid points; h1 staged once in
// smem; 4 warps split k 128-wide each -> W2 streamed once per block.
// unroll 1 keeps live set ~70 regs (NO spills).
// ---------------------------------------------------------------------------
__global__ void __launch_bounds__(128)
build_table(const float* __restrict__ W1, const float* __restrict__ b1,
            const float* __restrict__ W2, const float* __restrict__ b2,
            const float* __restrict__ W3, const float* __restrict__ b3)
{
    __shared__ __align__(16) float h1s[8][HID];   // 16 KB
    __shared__ float part[4][8];
    const int tid  = threadIdx.x;
    const int warp = tid >> 5;
    const int lane = tid & 31;
    const int m0   = blockIdx.x * 8;

    // stage h1 = tanh([t,y] @ W1 + b1) for the 8 rows, cooperatively
    for (int idx = tid; idx < 8 * HID; idx += 128) {
        int r = idx >> 9;                 // HID = 512
        int j = idx & (HID - 1);
        int m = m0 + r;
        float t  = (float)(m >> 7) * (1.0f / (float)(NT - 1));   // GY = 128
        float yv = YLO + (float)(m & (GY - 1)) * ((YHI - YLO) / (float)(GY - 1));
        h1s[r][j] = tanhf(t * W1[j] + yv * W1[HID + j] + b1[j]);
    }
    __syncthreads();

    const int kbase = warp * 128;
    float fs[8];
    #pragma unroll
    for (int r = 0; r < 8; ++r) fs[r] = 0.f;

    #pragma unroll 1
    for (int kc = 0; kc < 4; ++kc) {
        const int k = kbase + kc * 32 + lane;
        float a[8];
        float bk = b2[k];
        #pragma unroll
        for (int r = 0; r < 8; ++r) a[r] = bk;

        const float* __restrict__ wcol = W2 + k;
        #pragma unroll 1
        for (int j4 = 0; j4 < HID / 4; ++j4) {
            float4 v[8];
            #pragma unroll
            for (int r = 0; r < 8; ++r)
                v[r] = ((const float4*)h1s[r])[j4];   // lane-uniform broadcast
            const float* wr = wcol + (j4 * 4) * HID;
            float w;
            w = wr[0];
            #pragma unroll
            for (int r = 0; r < 8; ++r) a[r] += v[r].x * w;
            w = wr[HID];
            #pragma unroll
            for (int r = 0; r < 8; ++r) a[r] += v[r].y * w;
            w = wr[2 * HID];
            #pragma unroll
            for (int r = 0; r < 8; ++r) a[r] += v[r].z * w;
            w = wr[3 * HID];
            #pragma unroll
            for (int r = 0; r < 8; ++r) a[r] += v[r].w * w;
        }
        float wk = W3[k];
        #pragma unroll
        for (int r = 0; r < 8; ++r)
            fs[r] += tanhf(a[r]) * wk;
    }

    // deterministic lane reduction, then cross-warp combine via smem
    #pragma unroll
    for (int off = 16; off > 0; off >>= 1) {
        #pragma unroll
        for (int r = 0; r < 8; ++r)
            fs[r] += __shfl_xor_sync(0xFFFFFFFFu, fs[r], off);
    }
    if (lane == 0) {
        #pragma unroll
        for (int r = 0; r < 8; ++r) part[warp][r] = fs[r];
    }
    __syncthreads();
    if (tid < 8) {
        g_Fc[m0 + tid] = part[0][tid] + part[1][tid] + part[2][tid]
                       + part[3][tid] + b3[0];
    }
}

// ---------------------------------------------------------------------------
// Kernel 2a: expand coarse t-grid to per-step node values (4-pt Lagrange in t)
// ---------------------------------------------------------------------------
__global__ void expand_vals()
{
    int idx = blockIdx.x * blockDim.x + threadIdx.x;
    if (idx >= STEPS * GY) return;
    int s = idx / GY;
    int g = idx - s * GY;
    float t = (float)s * DT_F;
    float xf = t * (float)(NT - 1);
    int i = (int)floorf(xf);
    i = min(max(i, 1), NT - 3);
    float a = xf - (float)i;
    float wm1 = -a * (a - 1.f) * (a - 2.f) * (1.f / 6.f);
    float w0  = (a + 1.f) * (a - 1.f) * (a - 2.f) * 0.5f;
    float w1  = -(a + 1.f) * a * (a - 2.f) * 0.5f;
    float w2  = (a + 1.f) * a * (a - 1.f) * (1.f / 6.f);
    g_Fv[idx] = wm1 * g_Fc[(i - 1) * GY + g] + w0 * g_Fc[i * GY + g]
              + w1  * g_Fc[(i + 1) * GY + g] + w2 * g_Fc[(i + 2) * GY + g];
}

// ---------------------------------------------------------------------------
// Kernel 2b: node values -> power-basis cubic coeffs per (step, cell).
// Cell i stencil {i-1, i, i+1, i+2}; local variable a in [-0.5, 0.5] around i.
// ---------------------------------------------------------------------------
__global__ void expand_coef()
{
    int idx = blockIdx.x * blockDim.x + threadIdx.x;
    if (idx >= STEPS * GY) return;
    int s = idx / GY;
    int i = idx - s * GY;
    const float* row = g_Fv + s * GY;
    int jm1 = max(i - 1, 0);
    int jp1 = min(i + 1, GY - 1);
    int jp2 = min(i + 2, GY - 1);
    float f0 = row[jm1], f1 = row[i], f2 = row[jp1], f3 = row[jp2];
    float4 c;
    c.x = f1;                                                   // a^0
    c.y = -f0 * (1.f / 3.f) - 0.5f * f1 + f2 - f3 * (1.f / 6.f);// a^1
    c.z = 0.5f * f0 - f1 + 0.5f * f2;                           // a^2
    c.w = (f3 - f0) * (1.f / 6.f) + 0.5f * (f1 - f2);           // a^3
    g_C[idx] = c;
}

// ---------------------------------------------------------------------------
// Kernel 3: simulation. One thread per sample, all 1000 steps.
// Coeff rows staged via cp.async double-buffer; per step: magic-round index,
// one LDS.128, Horner cubic. dW front-batched; float4 output stores.
// ---------------------------------------------------------------------------
__global__ void __launch_bounds__(SIM_THREADS)
sim_kernel(const float* __restrict__ eps, const float* __restrict__ dW,
           const float* __restrict__ qm, const float* __restrict__ qlv,
           float* __restrict__ out)
{
    __shared__ __align__(16) float4 rows[2][CHUNK][GY];  // 32 KB
    __shared__ float red[SIM_THREADS];
    const int tid = threadIdx.x;
    const int b = blockIdx.x * SIM_THREADS + tid;

    float y = qm[0] + eps[b] * expf(0.5f * qlv[0]);
    float lq = 0.f;
    const float invH = (float)(GY - 1) / (YHI - YLO);
    const float offc = -YLO * invH;

    const int F4C = CHUNK * GY;               // float4 per chunk = 1024
    const int QN  = F4C / SIM_THREADS;        // 8 per thread

    uint32_t s0addr = (uint32_t)__cvta_generic_to_shared(&rows[0][0][0]);
    uint32_t s1addr = (uint32_t)__cvta_generic_to_shared(&rows[1][0][0]);

    // preload chunk 0
    #pragma unroll
    for (int q = 0; q < QN; ++q)
        cp_async16(s0addr + (tid + SIM_THREADS * q) * 16,
                   g_C + tid + SIM_THREADS * q);
    cp_commit();

    for (int c = 0; c < NCHUNK; ++c) {
        const int cur = c & 1;
        const int s0 = c * CHUNK;

        // issue prefetch of chunk c+1 into the other buffer
        if (c + 1 < NCHUNK) {
            uint32_t dsta = cur ? s0addr : s1addr;
            const float4* src = g_C + (c + 1) * F4C;
            #pragma unroll
            for (int q = 0; q < QN; ++q)
                cp_async16(dsta + (tid + SIM_THREADS * q) * 16,
                           src + tid + SIM_THREADS * q);
            cp_commit();
            cp_wait<1>();   // chunk c complete; c+1 may still be in flight
        } else {
            cp_wait<0>();
        }
        __syncthreads();

        // front-batched dW loads (DRAM stream, high MLP)
        float dwbuf[CHUNK];
        #pragma unroll
        for (int ii = 0; ii < CHUNK; ++ii)
            dwbuf[ii] = dW[(size_t)(s0 + ii) * BATCH + b];

        float buf[CHUNK];
        #pragma unroll
        for (int ii = 0; ii < CHUNK; ++ii) {
            float xf = fmaf(y, invH, offc);
            xf = fminf(fmaxf(xf, 1.501f), (float)(GY - 3) + 0.499f);
            float mg = xf + MAGIC;                    // RN(xf) in mantissa
            int bits = __float_as_int(mg);
            float a = xf - (mg - MAGIC);              // a in [-0.5, 0.5]
            const char* base = (const char*)rows[cur][ii];
            float4 cf = *(const float4*)(base + ((bits & 0x7F) << 4));
            float f = fmaf(fmaf(fmaf(cf.w, a, cf.z), a, cf.y), a, cf.x);
            // u = (f_post - theta*(mu - y)) / sigma ; theta=1, mu=1, sigma=.5
            float u = (f - 1.0f + y) * 2.0f;
            lq = fmaf(u * u, 0.5f * DT_F, lq);
            y = fmaf(f, DT_F, y) + 0.5f * dwbuf[ii];
            buf[ii] = y;
        }

        float4* dst = (float4*)(out + (size_t)b * STEPS + s0);
        dst[0] = make_float4(buf[0], buf[1], buf[2], buf[3]);
        dst[1] = make_float4(buf[4], buf[5], buf[6], buf[7]);

        __syncthreads();  // all reads of rows[cur] done before it is refilled
    }

    // deterministic block reduction of logqp
    red[tid] = lq;
    __syncthreads();
    #pragma unroll
    for (int off = SIM_THREADS / 2; off > 0; off >>= 1) {
        if (tid < off) red[tid] += red[tid + off];
        __syncthreads();
    }
    if (tid == 0) g_part[blockIdx.x] = red[0];
}

// ---------------------------------------------------------------------------
// Kernel 4: finalize -> logpq scalar at out[BATCH*STEPS]
// ---------------------------------------------------------------------------
__global__ void finalize_kernel(const float* __restrict__ qm,
                                const float* __restrict__ qlv,
                                float* __restrict__ out)
{
    __shared__ float red[SIM_BLOCKS];
    int t = threadIdx.x;
    red[t] = g_part[t];
    __syncthreads();
    #pragma unroll
    for (int off = SIM_BLOCKS / 2; off > 0; off >>= 1) {
        if (t < off) red[t] += red[t + off];
        __syncthreads();
    }
    if (t == 0) {
        float qstd  = expf(0.5f * qlv[0]);
        float pystd = 0.5f / sqrtf(2.0f);   // sigma / sqrt(2*theta)
        float r = qstd / pystd;
        float dm = 1.0f - qm[0];            // mu - qy0_mean
        float kl0 = 0.5f * (r * r + dm * dm / (pystd * pystd) - 1.0f + logf(pystd / qstd));
        out[(size_t)BATCH * STEPS] = kl0 + red[0] / (float)BATCH;
    }
}

// ---------------------------------------------------------------------------
extern "C" void kernel_launch(void* const* d_in, const int* in_sizes, int n_in,
                              void* d_out, int out_size)
{
    const float* W1  = (const float*)d_in[0];
    const float* b1  = (const float*)d_in[1];
    const float* W2  = (const float*)d_in[2];
    const float* b2  = (const float*)d_in[3];
    const float* W3  = (const float*)d_in[4];
    const float* b3  = (const float*)d_in[5];
    const float* qm  = (const float*)d_in[6];
    const float* qlv = (const float*)d_in[7];
    const float* eps = (const float*)d_in[8];
    const float* dW  = (const float*)d_in[9];
    float* out = (float*)d_out;

    build_table<<<NT * GY / 8, 128>>>(W1, b1, W2, b2, W3, b3);
    expand_vals<<<(STEPS * GY + 255) / 256, 256>>>();
    expand_coef<<<(STEPS * GY + 255) / 256, 256>>>();
    sim_kernel<<<SIM_BLOCKS, SIM_THREADS>>>(eps, dW, qm, qlv, out);
    finalize_kernel<<<1, SIM_BLOCKS>>>(qm, qlv, out);
}

// round 5
// speedup vs baseline: 9.2228x; 1.8084x over previous
#include <cuda_runtime.h>
#include <math.h>
#include <stdint.h>

#define BATCH 32768
#define STEPS 1000
#define HID   512
#define NT    16           // coarse t-grid points over [0,1]
#define GY    64           // y-grid points
#define EPTS  (NT * GY)    // 1024 coarse points
#define DT_F  0.001f
#define YLO  (-9.5f)
#define YHI  (11.5f)
#define CHUNK 10           // steps per staged chunk (1000 = 100*10)
#define NCHUNK (STEPS / CHUNK)
#define SIM_BLOCKS 256
#define SIM_THREADS 128
#define KSPLIT 4
#define MAGIC 12582912.0f  // 1.5 * 2^23

// scratch (static device arrays; no runtime allocation)
__device__ float  g_Fp[KSPLIT * EPTS];   // k-split partial sums
__device__ float  g_Fc[EPTS];            // coarse table f(t_i, y_g)
__device__ float  g_Fv[STEPS * GY];      // per-step node values
__device__ float4 g_C[STEPS * GY];       // per-step per-cell cubic coeffs
__device__ float  g_part[SIM_BLOCKS];    // logqp block partials

__device__ __forceinline__ void cp_async16(uint32_t saddr, const void* gaddr) {
    asm volatile("cp.async.cg.shared.global [%0], [%1], 16;\n" :: "r"(saddr), "l"(gaddr));
}
__device__ __forceinline__ void cp_commit() {
    asm volatile("cp.async.commit_group;\n");
}
template <int N>
__device__ __forceinline__ void cp_wait() {
    asm volatile("cp.async.wait_group %0;\n" :: "n"(N));
}

// ---------------------------------------------------------------------------
// Kernel 1: build coarse table, k-SPLIT across blocks for occupancy.
// Block (pg, kb): 8 grid points x 128 output neurons (k in [kb*128, kb*128+128)).
// h1 staged in smem; each of 4 warps owns a 32-wide k sub-slice; W2 quarter
// streamed once per block. Partial tanh(z2[k])*W3[k] sums -> g_Fp.
// ---------------------------------------------------------------------------
__global__ void __launch_bounds__(128)
build_partial(const float* __restrict__ W1, const float* __restrict__ b1,
              const float* __restrict__ W2, const float* __restrict__ b2,
              const float* __restrict__ W3)
{
    __shared__ __align__(16) float h1s[8][HID];   // 16 KB
    __shared__ float part[4][8];
    const int tid  = threadIdx.x;
    const int warp = tid >> 5;
    const int lane = tid & 31;
    const int pg   = blockIdx.x >> 2;
    const int kb   = blockIdx.x & 3;
    const int m0   = pg * 8;

    // stage h1 = tanh([t,y] @ W1 + b1) for the 8 rows, cooperatively
    for (int idx = tid; idx < 8 * HID; idx += 128) {
        int r = idx >> 9;                 // HID = 512
        int j = idx & (HID - 1);
        int m = m0 + r;
        float t  = (float)(m >> 6) * (1.0f / (float)(NT - 1));   // GY = 64
        float yv = YLO + (float)(m & (GY - 1)) * ((YHI - YLO) / (float)(GY - 1));
        h1s[r][j] = tanhf(t * W1[j] + yv * W1[HID + j] + b1[j]);
    }
    __syncthreads();

    const int k = kb * 128 + warp * 32 + lane;
    float a[8];
    float bk = b2[k];
    #pragma unroll
    for (int r = 0; r < 8; ++r) a[r] = bk;

    const float* __restrict__ wcol = W2 + k;
    #pragma unroll 1
    for (int j4 = 0; j4 < HID / 4; ++j4) {
        float4 v[8];
        #pragma unroll
        for (int r = 0; r < 8; ++r)
            v[r] = ((const float4*)h1s[r])[j4];   // lane-uniform broadcast
        const float* wr = wcol + (j4 * 4) * HID;
        float w;
        w = wr[0];
        #pragma unroll
        for (int r = 0; r < 8; ++r) a[r] += v[r].x * w;
        w = wr[HID];
        #pragma unroll
        for (int r = 0; r < 8; ++r) a[r] += v[r].y * w;
        w = wr[2 * HID];
        #pragma unroll
        for (int r = 0; r < 8; ++r) a[r] += v[r].z * w;
        w = wr[3 * HID];
        #pragma unroll
        for (int r = 0; r < 8; ++r) a[r] += v[r].w * w;
    }

    float wk = W3[k];
    float fs[8];
    #pragma unroll
    for (int r = 0; r < 8; ++r) fs[r] = tanhf(a[r]) * wk;

    // deterministic lane reduction, cross-warp combine via smem
    #pragma unroll
    for (int off = 16; off > 0; off >>= 1) {
        #pragma unroll
        for (int r = 0; r < 8; ++r)
            fs[r] += __shfl_xor_sync(0xFFFFFFFFu, fs[r], off);
    }
    if (lane == 0) {
        #pragma unroll
        for (int r = 0; r < 8; ++r) part[warp][r] = fs[r];
    }
    __syncthreads();
    if (tid < 8) {
        g_Fp[kb * EPTS + m0 + tid] =
            part[0][tid] + part[1][tid] + part[2][tid] + part[3][tid];
    }
}

// ---------------------------------------------------------------------------
// Kernel 1b: combine k-split partials + b3 -> coarse table
// ---------------------------------------------------------------------------
__global__ void combine_coarse(const float* __restrict__ b3)
{
    int i = blockIdx.x * blockDim.x + threadIdx.x;
    if (i < EPTS)
        g_Fc[i] = g_Fp[i] + g_Fp[EPTS + i] + g_Fp[2 * EPTS + i]
                + g_Fp[3 * EPTS + i] + b3[0];
}

// ---------------------------------------------------------------------------
// Kernel 2a: expand coarse t-grid to per-step node values (4-pt Lagrange in t)
// ---------------------------------------------------------------------------
__global__ void expand_vals()
{
    int idx = blockIdx.x * blockDim.x + threadIdx.x;
    if (idx >= STEPS * GY) return;
    int s = idx >> 6;            // GY = 64
    int g = idx & (GY - 1);
    float t = (float)s * DT_F;
    float xf = t * (float)(NT - 1);
    int i = (int)floorf(xf);
    i = min(max(i, 1), NT - 3);
    float a = xf - (float)i;
    float wm1 = -a * (a - 1.f) * (a - 2.f) * (1.f / 6.f);
    float w0  = (a + 1.f) * (a - 1.f) * (a - 2.f) * 0.5f;
    float w1  = -(a + 1.f) * a * (a - 2.f) * 0.5f;
    float w2  = (a + 1.f) * a * (a - 1.f) * (1.f / 6.f);
    g_Fv[idx] = wm1 * g_Fc[(i - 1) * GY + g] + w0 * g_Fc[i * GY + g]
              + w1  * g_Fc[(i + 1) * GY + g] + w2 * g_Fc[(i + 2) * GY + g];
}

// ---------------------------------------------------------------------------
// Kernel 2b: node values -> power-basis cubic coeffs per (step, cell).
// ---------------------------------------------------------------------------
__global__ void expand_coef()
{
    int idx = blockIdx.x * blockDim.x + threadIdx.x;
    if (idx >= STEPS * GY) return;
    int s = idx >> 6;
    int i = idx & (GY - 1);
    const float* row = g_Fv + s * GY;
    int jm1 = max(i - 1, 0);
    int jp1 = min(i + 1, GY - 1);
    int jp2 = min(i + 2, GY - 1);
    float f0 = row[jm1], f1 = row[i], f2 = row[jp1], f3 = row[jp2];
    float4 c;
    c.x = f1;
    c.y = -f0 * (1.f / 3.f) - 0.5f * f1 + f2 - f3 * (1.f / 6.f);
    c.z = 0.5f * f0 - f1 + 0.5f * f2;
    c.w = (f3 - f0) * (1.f / 6.f) + 0.5f * (f1 - f2);
    g_C[idx] = c;
}

// ---------------------------------------------------------------------------
// Kernel 3: simulation. One thread per sample, all 1000 steps.
// Software-pipelined: table chunk c+1 via cp.async AND dW chunk c+1 via LDG
// both issued at top of chunk c, consumed a full chunk later -> latency hidden.
// One barrier per chunk. Per step: magic-round, one LDS.128, Horner cubic.
// ---------------------------------------------------------------------------
__global__ void __launch_bounds__(SIM_THREADS)
sim_kernel(const float* __restrict__ eps, const float* __restrict__ dW,
           const float* __restrict__ qm, const float* __restrict__ qlv,
           float* __restrict__ out)
{
    __shared__ __align__(16) float4 rows[2][CHUNK][GY];  // 20 KB
    __shared__ float red[SIM_THREADS];
    const int tid = threadIdx.x;
    const int b = blockIdx.x * SIM_THREADS + tid;

    float y = qm[0] + eps[b] * expf(0.5f * qlv[0]);
    float lq = 0.f;
    const float invH = (float)(GY - 1) / (YHI - YLO);
    const float offc = -YLO * invH;

    const int F4C = CHUNK * GY;               // float4 per chunk = 640
    const int QN  = F4C / SIM_THREADS;        // 5 per thread

    uint32_t sA = (uint32_t)__cvta_generic_to_shared(&rows[0][0][0]);
    uint32_t sB = (uint32_t)__cvta_generic_to_shared(&rows[1][0][0]);

    // preload table chunk 0 + dW chunk 0
    #pragma unroll
    for (int q = 0; q < QN; ++q)
        cp_async16(sA + (tid + SIM_THREADS * q) * 16,
                   g_C + tid + SIM_THREADS * q);
    cp_commit();
    float dwreg[CHUNK];
    #pragma unroll
    for (int ii = 0; ii < CHUNK; ++ii)
        dwreg[ii] = dW[(size_t)ii * BATCH + b];

    for (int c = 0; c < NCHUNK; ++c) {
        cp_wait<0>();        // table chunk c complete (own group)
        __syncthreads();     // visible to all; all warps done reading buf (c-1)&1

        // issue table prefetch for chunk c+1 into the other buffer
        if (c + 1 < NCHUNK) {
            uint32_t dsta = (c & 1) ? sA : sB;     // (c+1)&1 buffer
            const float4* src = g_C + (c + 1) * F4C;
            #pragma unroll
            for (int q = 0; q < QN; ++q)
                cp_async16(dsta + (tid + SIM_THREADS * q) * 16,
                           src + tid + SIM_THREADS * q);
            cp_commit();
        }

        // issue dW prefetch for chunk c+1 (consumed next iteration)
        float dwn[CHUNK];
        if (c + 1 < NCHUNK) {
            const float* src = dW + (size_t)(c + 1) * CHUNK * BATCH + b;
            #pragma unroll
            for (int ii = 0; ii < CHUNK; ++ii)
                dwn[ii] = src[(size_t)ii * BATCH];
        }

        const float4* rbase = &rows[c & 1][0][0];
        float buf[CHUNK];
        #pragma unroll
        for (int ii = 0; ii < CHUNK; ++ii) {
            float xf = fmaf(y, invH, offc);
            xf = fminf(fmaxf(xf, 1.501f), (float)(GY - 3) + 0.499f);
            float mg = xf + MAGIC;                    // RN(xf) in mantissa
            int bits = __float_as_int(mg);
            float a = xf - (mg - MAGIC);              // a in (-0.5, 0.5)
            const char* base = (const char*)(rbase + ii * GY);
            float4 cf = *(const float4*)(base + ((bits & (GY - 1)) << 4));
            float f = fmaf(fmaf(fmaf(cf.w, a, cf.z), a, cf.y), a, cf.x);
            // u = (f_post - theta*(mu - y)) / sigma ; theta=1, mu=1, sigma=.5
            float u = (f - 1.0f + y) * 2.0f;
            lq = fmaf(u * u, 0.5f * DT_F, lq);
            y = fmaf(f, DT_F, y) + 0.5f * dwreg[ii];
            buf[ii] = y;
        }

        // 10 floats = 5 x STG.64 (8B-aligned: 1000*4 and 40*c both mult of 8)
        float2* dst = (float2*)(out + (size_t)b * STEPS + c * CHUNK);
        #pragma unroll
        for (int q = 0; q < CHUNK / 2; ++q)
            dst[q] = make_float2(buf[2 * q], buf[2 * q + 1]);

        if (c + 1 < NCHUNK) {
            #pragma unroll
            for (int ii = 0; ii < CHUNK; ++ii) dwreg[ii] = dwn[ii];
        }
    }

    // deterministic block reduction of logqp
    red[tid] = lq;
    __syncthreads();
    #pragma unroll
    for (int off = SIM_THREADS / 2; off > 0; off >>= 1) {
        if (tid < off) red[tid] += red[tid + off];
        __syncthreads();
    }
    if (tid == 0) g_part[blockIdx.x] = red[0];
}

// ---------------------------------------------------------------------------
// Kernel 4: finalize -> logpq scalar at out[BATCH*STEPS]
// ---------------------------------------------------------------------------
__global__ void finalize_kernel(const float* __restrict__ qm,
                                const float* __restrict__ qlv,
                                float* __restrict__ out)
{
    __shared__ float red[SIM_BLOCKS];
    int t = threadIdx.x;
    red[t] = g_part[t];
    __syncthreads();
    #pragma unroll
    for (int off = SIM_BLOCKS / 2; off > 0; off >>= 1) {
        if (t < off) red[t] += red[t + off];
        __syncthreads();
    }
    if (t == 0) {
        float qstd  = expf(0.5f * qlv[0]);
        float pystd = 0.5f / sqrtf(2.0f);   // sigma / sqrt(2*theta)
        float r = qstd / pystd;
        float dm = 1.0f - qm[0];            // mu - qy0_mean
        float kl0 = 0.5f * (r * r + dm * dm / (pystd * pystd) - 1.0f + logf(pystd / qstd));
        out[(size_t)BATCH * STEPS] = kl0 + red[0] / (float)BATCH;
    }
}

// ---------------------------------------------------------------------------
extern "C" void kernel_launch(void* const* d_in, const int* in_sizes, int n_in,
                              void* d_out, int out_size)
{
    const float* W1  = (const float*)d_in[0];
    const float* b1  = (const float*)d_in[1];
    const float* W2  = (const float*)d_in[2];
    const float* b2  = (const float*)d_in[3];
    const float* W3  = (const float*)d_in[4];
    const float* b3  = (const float*)d_in[5];
    const float* qm  = (const float*)d_in[6];
    const float* qlv = (const float*)d_in[7];
    const float* eps = (const float*)d_in[8];
    const float* dW  = (const float*)d_in[9];
    float* out = (float*)d_out;

    build_partial<<<(EPTS / 8) * KSPLIT, 128>>>(W1, b1, W2, b2, W3);
    combine_coarse<<<(EPTS + 255) / 256, 256>>>(b3);
    expand_vals<<<(STEPS * GY + 255) / 256, 256>>>();
    expand_coef<<<(STEPS * GY + 255) / 256, 256>>>();
    sim_kernel<<<SIM_BLOCKS, SIM_THREADS>>>(eps, dW, qm, qlv, out);
    finalize_kernel<<<1, SIM_BLOCKS>>>(qm, qlv, out);
}

// round 6
// speedup vs baseline: 12.9505x; 1.4042x over previous
#include <cuda_runtime.h>
#include <math.h>
#include <stdint.h>

#define BATCH 32768
#define HALFB 16384
#define STEPS 1000
#define HID   512
#define NT    8            // coarse t-grid points over [0,1]
#define GY    64           // y-grid points
#define EPTS  (NT * GY)    // 512 coarse points
#define DT_F  0.001f
#define YLO  (-9.5f)
#define YHI  (11.5f)
#define CHUNK 10           // steps per staged chunk (1000 = 100*10)
#define NCHUNK (STEPS / CHUNK)
#define SIM_BLOCKS 256
#define SIM_THREADS 64
#define KSPLIT 4
#define MAGIC 12582912.0f  // 1.5 * 2^23

// scratch (static device arrays; no runtime allocation)
__device__ float  g_Fp[KSPLIT * EPTS];   // k-split partial sums
__device__ float  g_Fc[EPTS];            // coarse table f(t_i, y_g)
__device__ float  g_Fv[STEPS * GY];      // per-step node values
__device__ float4 g_C[STEPS * GY];       // per-step per-cell cubic coeffs
__device__ float  g_part[SIM_BLOCKS];    // logqp block partials

__device__ __forceinline__ void cp_async16(uint32_t saddr, const void* gaddr) {
    asm volatile("cp.async.cg.shared.global [%0], [%1], 16;\n" :: "r"(saddr), "l"(gaddr));
}
__device__ __forceinline__ void cp_commit() {
    asm volatile("cp.async.commit_group;\n");
}
template <int N>
__device__ __forceinline__ void cp_wait() {
    asm volatile("cp.async.wait_group %0;\n" :: "n"(N));
}

// ---------------------------------------------------------------------------
// Kernel 1: build coarse table, k-split across blocks.
// Block (pg, kb): 8 grid points x 128 output neurons.
// ---------------------------------------------------------------------------
__global__ void __launch_bounds__(128)
build_partial(const float* __restrict__ W1, const float* __restrict__ b1,
              const float* __restrict__ W2, const float* __restrict__ b2,
              const float* __restrict__ W3)
{
    __shared__ __align__(16) float h1s[8][HID];   // 16 KB
    __shared__ float part[4][8];
    const int tid  = threadIdx.x;
    const int warp = tid >> 5;
    const int lane = tid & 31;
    const int pg   = blockIdx.x >> 2;
    const int kb   = blockIdx.x & 3;
    const int m0   = pg * 8;

    // stage h1 = tanh([t,y] @ W1 + b1) for the 8 rows, cooperatively
    for (int idx = tid; idx < 8 * HID; idx += 128) {
        int r = idx >> 9;                 // HID = 512
        int j = idx & (HID - 1);
        int m = m0 + r;
        float t  = (float)(m >> 6) * (1.0f / (float)(NT - 1));   // GY = 64
        float yv = YLO + (float)(m & (GY - 1)) * ((YHI - YLO) / (float)(GY - 1));
        h1s[r][j] = tanhf(t * W1[j] + yv * W1[HID + j] + b1[j]);
    }
    __syncthreads();

    const int k = kb * 128 + warp * 32 + lane;
    float a[8];
    float bk = b2[k];
    #pragma unroll
    for (int r = 0; r < 8; ++r) a[r] = bk;

    const float* __restrict__ wcol = W2 + k;
    #pragma unroll 1
    for (int j4 = 0; j4 < HID / 4; ++j4) {
        float4 v[8];
        #pragma unroll
        for (int r = 0; r < 8; ++r)
            v[r] = ((const float4*)h1s[r])[j4];   // lane-uniform broadcast
        const float* wr = wcol + (j4 * 4) * HID;
        float w;
        w = wr[0];
        #pragma unroll
        for (int r = 0; r < 8; ++r) a[r] += v[r].x * w;
        w = wr[HID];
        #pragma unroll
        for (int r = 0; r < 8; ++r) a[r] += v[r].y * w;
        w = wr[2 * HID];
        #pragma unroll
        for (int r = 0; r < 8; ++r) a[r] += v[r].z * w;
        w = wr[3 * HID];
        #pragma unroll
        for (int r = 0; r < 8; ++r) a[r] += v[r].w * w;
    }

    float wk = W3[k];
    float fs[8];
    #pragma unroll
    for (int r = 0; r < 8; ++r) fs[r] = tanhf(a[r]) * wk;

    #pragma unroll
    for (int off = 16; off > 0; off >>= 1) {
        #pragma unroll
        for (int r = 0; r < 8; ++r)
            fs[r] += __shfl_xor_sync(0xFFFFFFFFu, fs[r], off);
    }
    if (lane == 0) {
        #pragma unroll
        for (int r = 0; r < 8; ++r) part[warp][r] = fs[r];
    }
    __syncthreads();
    if (tid < 8) {
        g_Fp[kb * EPTS + m0 + tid] =
            part[0][tid] + part[1][tid] + part[2][tid] + part[3][tid];
    }
}

// ---------------------------------------------------------------------------
// Kernel 1b: combine k-split partials + b3 -> coarse table
// ---------------------------------------------------------------------------
__global__ void combine_coarse(const float* __restrict__ b3)
{
    int i = blockIdx.x * blockDim.x + threadIdx.x;
    if (i < EPTS)
        g_Fc[i] = g_Fp[i] + g_Fp[EPTS + i] + g_Fp[2 * EPTS + i]
                + g_Fp[3 * EPTS + i] + b3[0];
}

// ---------------------------------------------------------------------------
// Kernel 2a: expand coarse t-grid to per-step node values (4-pt Lagrange in t)
// ---------------------------------------------------------------------------
__global__ void expand_vals()
{
    int idx = blockIdx.x * blockDim.x + threadIdx.x;
    if (idx >= STEPS * GY) return;
    int s = idx >> 6;            // GY = 64
    int g = idx & (GY - 1);
    float t = (float)s * DT_F;
    float xf = t * (float)(NT - 1);
    int i = (int)floorf(xf);
    i = min(max(i, 1), NT - 3);
    float a = xf - (float)i;
    float wm1 = -a * (a - 1.f) * (a - 2.f) * (1.f / 6.f);
    float w0  = (a + 1.f) * (a - 1.f) * (a - 2.f) * 0.5f;
    float w1  = -(a + 1.f) * a * (a - 2.f) * 0.5f;
    float w2  = (a + 1.f) * a * (a - 1.f) * (1.f / 6.f);
    g_Fv[idx] = wm1 * g_Fc[(i - 1) * GY + g] + w0 * g_Fc[i * GY + g]
              + w1  * g_Fc[(i + 1) * GY + g] + w2 * g_Fc[(i + 2) * GY + g];
}

// ---------------------------------------------------------------------------
// Kernel 2b: node values -> power-basis cubic coeffs per (step, cell).
// ---------------------------------------------------------------------------
__global__ void expand_coef()
{
    int idx = blockIdx.x * blockDim.x + threadIdx.x;
    if (idx >= STEPS * GY) return;
    int s = idx >> 6;
    int i = idx & (GY - 1);
    const float* row = g_Fv + s * GY;
    int jm1 = max(i - 1, 0);
    int jp1 = min(i + 1, GY - 1);
    int jp2 = min(i + 2, GY - 1);
    float f0 = row[jm1], f1 = row[i], f2 = row[jp1], f3 = row[jp2];
    float4 c;
    c.x = f1;
    c.y = -f0 * (1.f / 3.f) - 0.5f * f1 + f2 - f3 * (1.f / 6.f);
    c.z = 0.5f * f0 - f1 + 0.5f * f2;
    c.w = (f3 - f0) * (1.f / 6.f) + 0.5f * (f1 - f2);
    g_C[idx] = c;
}

// ---------------------------------------------------------------------------
// Kernel 3: simulation. 64 threads/block, TWO samples per thread (b, b+16384)
// -> two independent dependency chains interleaved (2x chain ILP).
// Table AND dW chunks double-buffered in smem via cp.async (issued one chunk
// ahead). Outputs staged in smem, written out coalesced.
// ---------------------------------------------------------------------------
__global__ void __launch_bounds__(SIM_THREADS)
sim_kernel(const float* __restrict__ eps, const float* __restrict__ dW,
           const float* __restrict__ qm, const float* __restrict__ qlv,
           float* __restrict__ out)
{
    __shared__ __align__(16) float4 tabs[2][CHUNK][GY];        // 20 KB
    __shared__ __align__(16) float  dws[2][CHUNK][2][SIM_THREADS]; // 10 KB
    __shared__ __align__(16) float  ost[2][SIM_THREADS][CHUNK];    // 5 KB
    __shared__ float red[SIM_THREADS];

    const int tid = threadIdx.x;
    const int blkbase = blockIdx.x * SIM_THREADS;
    const int b0 = blkbase + tid;

    float qstd = expf(0.5f * qlv[0]);
    float qmv  = qm[0];
    float y0 = qmv + eps[b0] * qstd;
    float y1 = qmv + eps[b0 + HALFB] * qstd;
    float lq = 0.f;
    const float invH = (float)(GY - 1) / (YHI - YLO);
    const float offc = -YLO * invH;

    uint32_t tabA = (uint32_t)__cvta_generic_to_shared(&tabs[0][0][0]);
    uint32_t tabB = (uint32_t)__cvta_generic_to_shared(&tabs[1][0][0]);
    uint32_t dwA  = (uint32_t)__cvta_generic_to_shared(&dws[0][0][0][0]);
    uint32_t dwB  = (uint32_t)__cvta_generic_to_shared(&dws[1][0][0][0]);

    // ---- prefetch issuers ------------------------------------------------
    // table chunk: 640 float4 -> 10 per thread
    // dW chunk: [CHUNK][2 grp][64 floats] = 320 x 16B -> 5 per thread
    auto issue_chunk = [&](int c, uint32_t tdst, uint32_t ddst) {
        const float4* tsrc = g_C + c * (CHUNK * GY);
        #pragma unroll
        for (int q = 0; q < CHUNK * GY / SIM_THREADS; ++q)
            cp_async16(tdst + (tid + SIM_THREADS * q) * 16,
                       tsrc + tid + SIM_THREADS * q);
        const float* base = dW + (size_t)c * CHUNK * BATCH + blkbase;
        #pragma unroll
        for (int q = 0; q < 5; ++q) {
            int idx = tid + SIM_THREADS * q;      // 0..319
            int s   = idx >> 5;                   // step in chunk
            int r   = idx & 31;
            int grp = r >> 4;                     // 0 or 1
            int l   = r & 15;                     // 16B lane
            cp_async16(ddst + (uint32_t)(idx * 16),
                       base + (size_t)s * BATCH + grp * HALFB + l * 4);
        }
        cp_commit();
    };

    issue_chunk(0, tabA, dwA);

    for (int c = 0; c < NCHUNK; ++c) {
        const int cur = c & 1;
        cp_wait<0>();
        __syncthreads();   // chunk c data visible; ost/buffers free for reuse

        if (c + 1 < NCHUNK)
            issue_chunk(c + 1, cur ? tabA : tabB, cur ? dwA : dwB);

        const float4* tb = &tabs[cur][0][0];
        #pragma unroll
        for (int ii = 0; ii < CHUNK; ++ii) {
            // chain 0
            float xf0 = fmaf(y0, invH, offc);
            xf0 = fminf(fmaxf(xf0, 1.501f), (float)(GY - 3) + 0.499f);
            float mg0 = xf0 + MAGIC;
            int bt0 = __float_as_int(mg0);
            float a0 = xf0 - (mg0 - MAGIC);
            // chain 1
            float xf1 = fmaf(y1, invH, offc);
            xf1 = fminf(fmaxf(xf1, 1.501f), (float)(GY - 3) + 0.499f);
            float mg1 = xf1 + MAGIC;
            int bt1 = __float_as_int(mg1);
            float a1 = xf1 - (mg1 - MAGIC);

            const char* rb = (const char*)(tb + ii * GY);
            float4 c0 = *(const float4*)(rb + ((bt0 & (GY - 1)) << 4));
            float4 c1 = *(const float4*)(rb + ((bt1 & (GY - 1)) << 4));
            float f0 = fmaf(fmaf(fmaf(c0.w, a0, c0.z), a0, c0.y), a0, c0.x);
            float f1 = fmaf(fmaf(fmaf(c1.w, a1, c1.z), a1, c1.y), a1, c1.x);

            float u0 = (f0 - 1.0f + y0) * 2.0f;
            float u1 = (f1 - 1.0f + y1) * 2.0f;
            lq = fmaf(u0 * u0 + u1 * u1, 0.5f * DT_F, lq);

            y0 = fmaf(f0, DT_F, y0) + 0.5f * dws[cur][ii][0][tid];
            y1 = fmaf(f1, DT_F, y1) + 0.5f * dws[cur][ii][1][tid];
            ost[0][tid][ii] = y0;
            ost[1][tid][ii] = y1;
        }
        __syncthreads();   // ost complete before cooperative readout

        // coalesced write-out: 640 float2 (128 rows x 5 cols), 10 per thread
        #pragma unroll
        for (int q = 0; q < 10; ++q) {
            int idx = tid + SIM_THREADS * q;      // 0..639
            int row = idx / 5;                    // 0..127
            int col = idx - row * 5;
            int grp = row >> 6;
            int r   = row & 63;
            const float* src = &ost[grp][r][col * 2];
            float2 v = make_float2(src[0], src[1]);
            int sample = blkbase + grp * HALFB + r;
            *(float2*)(out + (size_t)sample * STEPS + c * CHUNK + col * 2) = v;
        }
    }

    // deterministic block reduction of logqp
    red[tid] = lq;
    __syncthreads();
    #pragma unroll
    for (int off = SIM_THREADS / 2; off > 0; off >>= 1) {
        if (tid < off) red[tid] += red[tid + off];
        __syncthreads();
    }
    if (tid == 0) g_part[blockIdx.x] = red[0];
}

// ---------------------------------------------------------------------------
// Kernel 4: finalize -> logpq scalar at out[BATCH*STEPS]
// ---------------------------------------------------------------------------
__global__ void finalize_kernel(const float* __restrict__ qm,
                                const float* __restrict__ qlv,
                                float* __restrict__ out)
{
    __shared__ float red[SIM_BLOCKS];
    int t = threadIdx.x;
    red[t] = g_part[t];
    __syncthreads();
    #pragma unroll
    for (int off = SIM_BLOCKS / 2; off > 0; off >>= 1) {
        if (t < off) red[t] += red[t + off];
        __syncthreads();
    }
    if (t == 0) {
        float qstd  = expf(0.5f * qlv[0]);
        float pystd = 0.5f / sqrtf(2.0f);   // sigma / sqrt(2*theta)
        float r = qstd / pystd;
        float dm = 1.0f - qm[0];            // mu - qy0_mean
        float kl0 = 0.5f * (r * r + dm * dm / (pystd * pystd) - 1.0f + logf(pystd / qstd));
        out[(size_t)BATCH * STEPS] = kl0 + red[0] / (float)BATCH;
    }
}

// ---------------------------------------------------------------------------
extern "C" void kernel_launch(void* const* d_in, const int* in_sizes, int n_in,
                              void* d_out, int out_size)
{
    const float* W1  = (const float*)d_in[0];
    const float* b1  = (const float*)d_in[1];
    const float* W2  = (const float*)d_in[2];
    const float* b2  = (const float*)d_in[3];
    const float* W3  = (const float*)d_in[4];
    const float* b3  = (const float*)d_in[5];
    const float* qm  = (const float*)d_in[6];
    const float* qlv = (const float*)d_in[7];
    const float* eps = (const float*)d_in[8];
    const float* dW  = (const float*)d_in[9];
    float* out = (float*)d_out;

    build_partial<<<(EPTS / 8) * KSPLIT, 128>>>(W1, b1, W2, b2, W3);
    combine_coarse<<<(EPTS + 255) / 256, 256>>>(b3);
    expand_vals<<<(STEPS * GY + 255) / 256, 256>>>();
    expand_coef<<<(STEPS * GY + 255) / 256, 256>>>();
    sim_kernel<<<SIM_BLOCKS, SIM_THREADS>>>(eps, dW, qm, qlv, out);
    finalize_kernel<<<1, SIM_BLOCKS>>>(qm, qlv, out);
}